// round 14
// baseline (speedup 1.0000x reference)
#include <cuda_runtime.h>
#include <cuda_bf16.h>
#include <cuda_fp16.h>
#include <cstdint>

#define BATCH 16
#define NPTS  4096
#define CIN   64
#define NSAMP 1024
#define KNBR  32
#define FULLM 0xffffffffu

// ---------------- f32x2 helpers (FPS only) ----------------
#define PACKF2(d, lo, hi)  asm("mov.b64 %0, {%1, %2};" : "=l"(d) : "f"(lo), "f"(hi))
#define UNPACKF2(lo, hi, s) asm("mov.b64 {%0, %1}, %2;" : "=f"(lo), "=f"(hi) : "l"(s))
#define ADD2(d, a, b) asm("add.rn.f32x2 %0, %1, %2;" : "=l"(d) : "l"(a), "l"(b))
#define MUL2(d, a, b) asm("mul.rn.f32x2 %0, %1, %2;" : "=l"(d) : "l"(a), "l"(b))

#define AMAX(vA, jA, vB, jB, vO, jO) { bool g_ = ((vB) > (vA)); (vO) = g_ ? (vB) : (vA); (jO) = g_ ? (jB) : (jA); }

// ---------------------------------------------------------------------------
// Kernel 1: FPS — R7 version (256 threads x 16 pts, 342us, bit-exact)
// ---------------------------------------------------------------------------
__global__ __launch_bounds__(256) void fps_kernel(const float* __restrict__ xyz,
                                                  float* __restrict__ new_xyz)
{
    extern __shared__ float sm[];
    float4* sxyz = (float4*)sm;
    unsigned long long* sred = (unsigned long long*)(sm + NPTS * 4);

    const int b = blockIdx.x, tid = threadIdx.x;
    const int lane = tid & 31, warp = tid >> 5;
    const float* gx = xyz + (size_t)b * NPTS * 3;

    for (int i = tid; i < NPTS; i += 256) {
        float4 v;
        v.x = gx[3 * i]; v.y = gx[3 * i + 1]; v.z = gx[3 * i + 2]; v.w = 0.f;
        sxyz[i] = v;
    }
    __syncthreads();

    unsigned long long px[8], py[8], pz[8];
    float dist[16];
#pragma unroll
    for (int q = 0; q < 8; q++) {
        float4 a = sxyz[tid + (2 * q) * 256];
        float4 c = sxyz[tid + (2 * q + 1) * 256];
        PACKF2(px[q], a.x, c.x);
        PACKF2(py[q], a.y, c.y);
        PACKF2(pz[q], a.z, c.z);
        dist[2 * q] = 1e10f; dist[2 * q + 1] = 1e10f;
    }

    int far = 0;
    for (int t = 0; t < NSAMP; t++) {
        float4 cen = sxyz[far];
        if (tid == 0) {
            float* o = new_xyz + ((size_t)b * NSAMP + t) * 3;
            o[0] = cen.x; o[1] = cen.y; o[2] = cen.z;
        }
        unsigned long long ncx, ncy, ncz;
        float mx = -cen.x, my = -cen.y, mz = -cen.z;
        PACKF2(ncx, mx, mx); PACKF2(ncy, my, my); PACKF2(ncz, mz, mz);

        float v[16];
#pragma unroll
        for (int q = 0; q < 8; q++) {
            unsigned long long dx, dy, dz, xx, yy, zz, s, d2;
            ADD2(dx, px[q], ncx);
            ADD2(dy, py[q], ncy);
            ADD2(dz, pz[q], ncz);
            MUL2(xx, dx, dx); MUL2(yy, dy, dy); MUL2(zz, dz, dz);
            ADD2(s, xx, yy); ADD2(d2, s, zz);
            float d0, d1;
            UNPACKF2(d0, d1, d2);
            float n0 = fminf(dist[2 * q], d0);     dist[2 * q] = n0;     v[2 * q] = n0;
            float n1 = fminf(dist[2 * q + 1], d1); dist[2 * q + 1] = n1; v[2 * q + 1] = n1;
        }
        float va[8]; int ja[8];
#pragma unroll
        for (int q = 0; q < 8; q++) AMAX(v[2 * q], 2 * q, v[2 * q + 1], 2 * q + 1, va[q], ja[q]);
        float vb[4]; int jb[4];
#pragma unroll
        for (int q = 0; q < 4; q++) AMAX(va[2 * q], ja[2 * q], va[2 * q + 1], ja[2 * q + 1], vb[q], jb[q]);
        float vc0, vc1; int jc0, jc1;
        AMAX(vb[0], jb[0], vb[1], jb[1], vc0, jc0);
        AMAX(vb[2], jb[2], vb[3], jb[3], vc1, jc1);
        float mv; int mj;
        AMAX(vc0, jc0, vc1, jc1, mv, mj);
        int bi = tid + mj * 256;

        unsigned bits = __float_as_uint(mv);
        unsigned wmax = __reduce_max_sync(FULLM, bits);
        unsigned cand = (bits == wmax) ? (unsigned)(4095 - bi) : 0u;
        unsigned winv = __reduce_max_sync(FULLM, cand);

        const int pt = t & 1;
        if (lane == 0)
            sred[pt * 8 + warp] = ((unsigned long long)wmax << 32) | winv;
        __syncthreads();
        const ulonglong2* kr = (const ulonglong2*)(sred + pt * 8);
        ulonglong2 k0 = kr[0], k1 = kr[1], k2 = kr[2], k3 = kr[3];
        unsigned long long m0 = k0.x > k0.y ? k0.x : k0.y;
        unsigned long long m1 = k1.x > k1.y ? k1.x : k1.y;
        unsigned long long m2 = k2.x > k2.y ? k2.x : k2.y;
        unsigned long long m3 = k3.x > k3.y ? k3.x : k3.y;
        unsigned long long ma = m0 > m1 ? m0 : m1;
        unsigned long long mb = m2 > m3 ? m2 : m3;
        unsigned long long mm = ma > mb ? ma : mb;
        far = 4095 - (int)(unsigned)(mm & 0xffffffffull);
    }
}

// ---------------------------------------------------------------------------
// Kernel 2: fused ball-query + MLP + maxpool. 1 centroid per warp, 2048
// blocks. Query indices staged in the warp's act smem (no global d_ball).
// Single-term fp16 mma path (numerics identical to R13).
// ---------------------------------------------------------------------------
#define ASTRIDE  176
#define WSTR1    176
#define WSTR23   144
#define SM_BIAS  0
#define SM_W1F   1024          // 64 x 176B -> 11264
#define SM_W2F   12288         // 64 x 144B -> 9216
#define SM_W3F   21504         // 128 x 144B -> 18432
#define SM_ACT   39936         // 8 warps x 5632B
#define ACTW     5632
#define SM_MLP_END (39936 + 8 * ACTW)   // 84992

__device__ __forceinline__ unsigned cvtf16(float lo, float hi) {
    unsigned r;
    asm("cvt.rn.f16x2.f32 %0, %1, %2;" : "=r"(r) : "f"(hi), "f"(lo));
    return r;
}
__device__ __forceinline__ uint32_t smem_u32(const void* p) {
    uint32_t a;
    asm("{ .reg .u64 t; cvta.to.shared.u64 t, %1; cvt.u32.u64 %0, t; }" : "=r"(a) : "l"(p));
    return a;
}
__device__ __forceinline__ void ldsm4(uint32_t* r, uint32_t addr) {
    asm volatile("ldmatrix.sync.aligned.m8n8.x4.shared.b16 {%0,%1,%2,%3}, [%4];"
        : "=r"(r[0]), "=r"(r[1]), "=r"(r[2]), "=r"(r[3]) : "r"(addr));
}
__device__ __forceinline__ void ldsm2(uint32_t* r, uint32_t addr) {
    asm volatile("ldmatrix.sync.aligned.m8n8.x2.shared.b16 {%0,%1}, [%2];"
        : "=r"(r[0]), "=r"(r[1]) : "r"(addr));
}
__device__ __forceinline__ void mma_f16(float* d, const uint32_t* a, const uint32_t* b) {
    asm volatile("mma.sync.aligned.m16n8k16.row.col.f32.f16.f16.f32 "
        "{%0,%1,%2,%3}, {%4,%5,%6,%7}, {%8,%9}, {%0,%1,%2,%3};"
        : "+f"(d[0]), "+f"(d[1]), "+f"(d[2]), "+f"(d[3])
        : "r"(a[0]), "r"(a[1]), "r"(a[2]), "r"(a[3]), "r"(b[0]), "r"(b[1]));
}

__device__ __forceinline__ void run_layer1_1t(uint32_t aH, uint32_t wFb,
                                              float acc[2][8][4])
{
#pragma unroll
    for (int m = 0; m < 2; m++)
#pragma unroll
        for (int n = 0; n < 8; n++)
#pragma unroll
            for (int q = 0; q < 4; q++) acc[m][n][q] = 0.f;
#pragma unroll
    for (int k = 0; k < 5; k++) {
        uint32_t ah[2][4];
        ldsm4(ah[0], aH + k * 32);
        ldsm4(ah[1], aH + 16 * ASTRIDE + k * 32);
        uint32_t bw[8][2];
#pragma unroll
        for (int n = 0; n < 8; n++)
            ldsm2(bw[n], wFb + n * 8 * WSTR1 + k * 32);
#pragma unroll
        for (int n = 0; n < 8; n++)
#pragma unroll
            for (int m = 0; m < 2; m++)
                mma_f16(acc[m][n], ah[m], bw[n]);
    }
}

__device__ __forceinline__ void build_frag_1t(const float acc[2][8][4],
                                              const float* bias, int cg,
                                              uint32_t af[2][4][4])
{
#pragma unroll
    for (int m = 0; m < 2; m++) {
#pragma unroll
        for (int j = 0; j < 4; j++) {
            const float* a0 = acc[m][2 * j];
            const float* a1 = acc[m][2 * j + 1];
            float bA0 = bias[(2 * j) * 8 + 2 * cg],     bB0 = bias[(2 * j) * 8 + 2 * cg + 1];
            float bA1 = bias[(2 * j + 1) * 8 + 2 * cg], bB1 = bias[(2 * j + 1) * 8 + 2 * cg + 1];
            float x0 = fmaxf(a0[0] + bA0, 0.f), x1 = fmaxf(a0[1] + bB0, 0.f);
            float x2 = fmaxf(a0[2] + bA0, 0.f), x3 = fmaxf(a0[3] + bB0, 0.f);
            float x4 = fmaxf(a1[0] + bA1, 0.f), x5 = fmaxf(a1[1] + bB1, 0.f);
            float x6 = fmaxf(a1[2] + bA1, 0.f), x7 = fmaxf(a1[3] + bB1, 0.f);
            af[m][j][0] = cvtf16(x0, x1);
            af[m][j][1] = cvtf16(x2, x3);
            af[m][j][2] = cvtf16(x4, x5);
            af[m][j][3] = cvtf16(x6, x7);
        }
    }
}

__device__ __forceinline__ void run_layer_1t(const uint32_t af[2][4][4],
                                             uint32_t wFb,
                                             float acc[2][8][4])
{
#pragma unroll
    for (int m = 0; m < 2; m++)
#pragma unroll
        for (int n = 0; n < 8; n++)
#pragma unroll
            for (int q = 0; q < 4; q++) acc[m][n][q] = 0.f;
#pragma unroll
    for (int k = 0; k < 4; k++) {
        uint32_t bw[8][2];
#pragma unroll
        for (int n = 0; n < 8; n++)
            ldsm2(bw[n], wFb + n * 8 * WSTR23 + k * 32);
#pragma unroll
        for (int n = 0; n < 8; n++)
#pragma unroll
            for (int m = 0; m < 2; m++)
                mma_f16(acc[m][n], af[m][k], bw[n]);
    }
}

__device__ __forceinline__ void epi_max(float acc[2][8][4], const float* bias,
                                        float* outp, int nbase, int lane)
{
    const int cg = lane & 3;
#pragma unroll
    for (int n = 0; n < 8; n++) {
        int n0 = nbase + n * 8 + 2 * cg;
        float b0v = bias[n0], b1v = bias[n0 + 1];
        float v0 = fmaxf(fmaxf(acc[0][n][0] + b0v, 0.f), fmaxf(acc[0][n][2] + b0v, 0.f));
        v0 = fmaxf(v0, fmaxf(fmaxf(acc[1][n][0] + b0v, 0.f), fmaxf(acc[1][n][2] + b0v, 0.f)));
        float v1 = fmaxf(fmaxf(acc[0][n][1] + b1v, 0.f), fmaxf(acc[0][n][3] + b1v, 0.f));
        v1 = fmaxf(v1, fmaxf(fmaxf(acc[1][n][1] + b1v, 0.f), fmaxf(acc[1][n][3] + b1v, 0.f)));
#pragma unroll
        for (int o = 4; o <= 16; o <<= 1) {
            v0 = fmaxf(v0, __shfl_xor_sync(FULLM, v0, o));
            v1 = fmaxf(v1, __shfl_xor_sync(FULLM, v1, o));
        }
        if (lane < 4) { outp[n0] = v0; outp[n0 + 1] = v1; }
    }
}

__global__ __launch_bounds__(256) void fused_kernel(
    const float* __restrict__ xyz, const float* __restrict__ pts,
    const float* __restrict__ w0, const float* __restrict__ b0,
    const float* __restrict__ w1, const float* __restrict__ b1,
    const float* __restrict__ w2, const float* __restrict__ b2,
    const float* __restrict__ new_xyz, float* __restrict__ new_points)
{
    extern __shared__ char smem[];
    const uint32_t sb = smem_u32(smem);
    const int tid = threadIdx.x, wid = tid >> 5, lane = tid & 31;

    float* b0s = (float*)(smem + SM_BIAS);
    float* b1s = b0s + 64;
    float* b2s = b1s + 64;
    if (tid < 64) { b0s[tid] = b0[tid]; b1s[tid] = b1[tid]; }
    if (tid < 128) b2s[tid] = b2[tid];

    for (int idx = tid; idx < 64 * 80; idx += 256) {
        int n = idx / 80, k = idx - n * 80;
        float w = (k < 67) ? w0[k * 64 + n] : 0.f;
        *(unsigned short*)(smem + SM_W1F + n * WSTR1 + k * 2) =
            __half_as_ushort(__float2half_rn(w));
    }
    for (int idx = tid; idx < 64 * 64; idx += 256) {
        int n = idx >> 6, k = idx & 63;
        *(unsigned short*)(smem + SM_W2F + n * WSTR23 + k * 2) =
            __half_as_ushort(__float2half_rn(w1[k * 64 + n]));
    }
    for (int idx = tid; idx < 128 * 64; idx += 256) {
        int n = idx >> 6, k = idx & 63;
        *(unsigned short*)(smem + SM_W3F + n * WSTR23 + k * 2) =
            __half_as_ushort(__float2half_rn(w2[k * 128 + n]));
    }
    __syncthreads();

    char* actHp = smem + SM_ACT + wid * ACTW;
    const uint32_t actH_u = sb + SM_ACT + wid * ACTW;
    const uint32_t aH = actH_u + (lane & 15) * ASTRIDE + (lane >> 4) * 16;
    const int bl = lane & 15;
    const uint32_t wl1 = (bl & 7) * WSTR1  + ((bl >> 3) & 1) * 16;
    const uint32_t wl2 = (bl & 7) * WSTR23 + ((bl >> 3) & 1) * 16;
    const uint32_t w1F = sb + SM_W1F + wl1;
    const uint32_t w2F = sb + SM_W2F + wl2;
    const uint32_t w3F = sb + SM_W3F + wl2;
    const int cg = lane & 3;

    const int centroid = blockIdx.x * 8 + wid;
    const int b = centroid >> 10;
    const float* gx = xyz + (size_t)b * NPTS * 3;
    const float* nc = new_xyz + (size_t)centroid * 3;
    const float cx = nc[0], cy = nc[1], cz = nc[2];

    // ---- ball query (indices staged in this warp's act smem) ----
    {
        int* ib = (int*)actHp;
        const float R2 = 0.04f;
        int cnt = 0, first = -1;
        for (int base = 0; base < NPTS && cnt < KNBR; base += 32) {
            int j = base + lane;
            float dx = __fsub_rn(cx, gx[3 * j]);
            float dy = __fsub_rn(cy, gx[3 * j + 1]);
            float dz = __fsub_rn(cz, gx[3 * j + 2]);
            float d2 = __fadd_rn(__fadd_rn(__fmul_rn(dx, dx), __fmul_rn(dy, dy)),
                                 __fmul_rn(dz, dz));
            bool in = (d2 <= R2);
            unsigned m = __ballot_sync(FULLM, in);
            int pos = cnt + __popc(m & ((1u << lane) - 1u));
            if (in && pos < KNBR) {
                ib[pos] = j;
                if (pos == 0) first = j;
            }
            cnt += __popc(m);
        }
        unsigned hf = __ballot_sync(FULLM, first >= 0);
        int src = __ffs(hf) - 1;
        first = __shfl_sync(FULLM, first, src);
        int filled = cnt < KNBR ? cnt : KNBR;
        if (lane >= filled) ib[lane] = first;
    }
    __syncwarp();
    const int nid = ((int*)actHp)[lane];
    __syncwarp();   // all lanes have read their index before rows overwrite

    // ---- gather: 64 features + 3 rel coords, pad to 80; fp16 rows ----
    {
        float arr[80];
        const float4* pr = (const float4*)(pts + ((size_t)b * NPTS + nid) * CIN);
#pragma unroll
        for (int q = 0; q < 16; q++) {
            float4 v = pr[q];
            arr[4 * q] = v.x; arr[4 * q + 1] = v.y; arr[4 * q + 2] = v.z; arr[4 * q + 3] = v.w;
        }
        const float* xr = gx + (size_t)nid * 3;
        arr[64] = __fsub_rn(xr[0], cx);
        arr[65] = __fsub_rn(xr[1], cy);
        arr[66] = __fsub_rn(xr[2], cz);
#pragma unroll
        for (int i = 67; i < 80; i++) arr[i] = 0.f;

        uint32_t* rowH = (uint32_t*)(actHp + lane * ASTRIDE);
#pragma unroll
        for (int i = 0; i < 40; i++)
            rowH[i] = cvtf16(arr[2 * i], arr[2 * i + 1]);
    }
    __syncwarp();

    float acc[2][8][4];
    run_layer1_1t(aH, w1F, acc);

    uint32_t af[2][4][4];
    build_frag_1t(acc, b0s, cg, af);
    run_layer_1t(af, w2F, acc);
    build_frag_1t(acc, b1s, cg, af);
    float* outp = new_points + (size_t)centroid * 128;
    run_layer_1t(af, w3F, acc);
    epi_max(acc, b2s, outp, 0, lane);
    run_layer_1t(af, w3F + 64 * WSTR23, acc);
    epi_max(acc, b2s, outp, 64, lane);
}

// ---------------------------------------------------------------------------
extern "C" void kernel_launch(void* const* d_in, const int* in_sizes, int n_in,
                              void* d_out, int out_size)
{
    (void)in_sizes; (void)n_in; (void)out_size;
    const float* xyz = (const float*)d_in[0];
    const float* pts = (const float*)d_in[1];
    const float* w0  = (const float*)d_in[2];
    const float* b0  = (const float*)d_in[3];
    const float* w1  = (const float*)d_in[4];
    const float* b1  = (const float*)d_in[5];
    const float* w2  = (const float*)d_in[6];
    const float* b2  = (const float*)d_in[7];

    float* out      = (float*)d_out;
    float* new_xyz  = out;
    float* new_pts  = out + (size_t)BATCH * NSAMP * 3;

    const int FPS_SMEM = NPTS * 16 + 128;
    const int MLP_SMEM = SM_MLP_END;

    cudaFuncSetAttribute(fps_kernel, cudaFuncAttributeMaxDynamicSharedMemorySize, FPS_SMEM);
    cudaFuncSetAttribute(fused_kernel, cudaFuncAttributeMaxDynamicSharedMemorySize, MLP_SMEM);

    fps_kernel<<<BATCH, 256, FPS_SMEM>>>(xyz, new_xyz);
    fused_kernel<<<(BATCH * NSAMP) / 8, 256, MLP_SMEM>>>(
        xyz, pts, w0, b0, w1, b1, w2, b2, new_xyz, new_pts);
}

// round 15
// speedup vs baseline: 1.4908x; 1.4908x over previous
#include <cuda_runtime.h>
#include <cuda_bf16.h>
#include <cuda_fp16.h>
#include <cstdint>

#define BATCH 16
#define NPTS  4096
#define CIN   64
#define NSAMP 1024
#define KNBR  32
#define FULLM 0xffffffffu

// ---------------- f32x2 helpers (FPS only) ----------------
#define PACKF2(d, lo, hi)  asm("mov.b64 %0, {%1, %2};" : "=l"(d) : "f"(lo), "f"(hi))
#define UNPACKF2(lo, hi, s) asm("mov.b64 {%0, %1}, %2;" : "=f"(lo), "=f"(hi) : "l"(s))
#define ADD2(d, a, b) asm("add.rn.f32x2 %0, %1, %2;" : "=l"(d) : "l"(a), "l"(b))
#define MUL2(d, a, b) asm("mul.rn.f32x2 %0, %1, %2;" : "=l"(d) : "l"(a), "l"(b))

__device__ int d_ball[BATCH * NSAMP * KNBR];

#define AMAX(vA, jA, vB, jB, vO, jO) { bool g_ = ((vB) > (vA)); (vO) = g_ ? (vB) : (vA); (jO) = g_ ? (jB) : (jA); }

// ---------------------------------------------------------------------------
// Kernel 1: FPS — R7 version (256 threads x 16 pts, 342us, bit-exact)
// ---------------------------------------------------------------------------
__global__ __launch_bounds__(256) void fps_kernel(const float* __restrict__ xyz,
                                                  float* __restrict__ new_xyz)
{
    extern __shared__ float sm[];
    float4* sxyz = (float4*)sm;
    unsigned long long* sred = (unsigned long long*)(sm + NPTS * 4);

    const int b = blockIdx.x, tid = threadIdx.x;
    const int lane = tid & 31, warp = tid >> 5;
    const float* gx = xyz + (size_t)b * NPTS * 3;

    for (int i = tid; i < NPTS; i += 256) {
        float4 v;
        v.x = gx[3 * i]; v.y = gx[3 * i + 1]; v.z = gx[3 * i + 2]; v.w = 0.f;
        sxyz[i] = v;
    }
    __syncthreads();

    unsigned long long px[8], py[8], pz[8];
    float dist[16];
#pragma unroll
    for (int q = 0; q < 8; q++) {
        float4 a = sxyz[tid + (2 * q) * 256];
        float4 c = sxyz[tid + (2 * q + 1) * 256];
        PACKF2(px[q], a.x, c.x);
        PACKF2(py[q], a.y, c.y);
        PACKF2(pz[q], a.z, c.z);
        dist[2 * q] = 1e10f; dist[2 * q + 1] = 1e10f;
    }

    int far = 0;
    for (int t = 0; t < NSAMP; t++) {
        float4 cen = sxyz[far];
        if (tid == 0) {
            float* o = new_xyz + ((size_t)b * NSAMP + t) * 3;
            o[0] = cen.x; o[1] = cen.y; o[2] = cen.z;
        }
        unsigned long long ncx, ncy, ncz;
        float mx = -cen.x, my = -cen.y, mz = -cen.z;
        PACKF2(ncx, mx, mx); PACKF2(ncy, my, my); PACKF2(ncz, mz, mz);

        float v[16];
#pragma unroll
        for (int q = 0; q < 8; q++) {
            unsigned long long dx, dy, dz, xx, yy, zz, s, d2;
            ADD2(dx, px[q], ncx);
            ADD2(dy, py[q], ncy);
            ADD2(dz, pz[q], ncz);
            MUL2(xx, dx, dx); MUL2(yy, dy, dy); MUL2(zz, dz, dz);
            ADD2(s, xx, yy); ADD2(d2, s, zz);
            float d0, d1;
            UNPACKF2(d0, d1, d2);
            float n0 = fminf(dist[2 * q], d0);     dist[2 * q] = n0;     v[2 * q] = n0;
            float n1 = fminf(dist[2 * q + 1], d1); dist[2 * q + 1] = n1; v[2 * q + 1] = n1;
        }
        float va[8]; int ja[8];
#pragma unroll
        for (int q = 0; q < 8; q++) AMAX(v[2 * q], 2 * q, v[2 * q + 1], 2 * q + 1, va[q], ja[q]);
        float vb[4]; int jb[4];
#pragma unroll
        for (int q = 0; q < 4; q++) AMAX(va[2 * q], ja[2 * q], va[2 * q + 1], ja[2 * q + 1], vb[q], jb[q]);
        float vc0, vc1; int jc0, jc1;
        AMAX(vb[0], jb[0], vb[1], jb[1], vc0, jc0);
        AMAX(vb[2], jb[2], vb[3], jb[3], vc1, jc1);
        float mv; int mj;
        AMAX(vc0, jc0, vc1, jc1, mv, mj);
        int bi = tid + mj * 256;

        unsigned bits = __float_as_uint(mv);
        unsigned wmax = __reduce_max_sync(FULLM, bits);
        unsigned cand = (bits == wmax) ? (unsigned)(4095 - bi) : 0u;
        unsigned winv = __reduce_max_sync(FULLM, cand);

        const int pt = t & 1;
        if (lane == 0)
            sred[pt * 8 + warp] = ((unsigned long long)wmax << 32) | winv;
        __syncthreads();
        const ulonglong2* kr = (const ulonglong2*)(sred + pt * 8);
        ulonglong2 k0 = kr[0], k1 = kr[1], k2 = kr[2], k3 = kr[3];
        unsigned long long m0 = k0.x > k0.y ? k0.x : k0.y;
        unsigned long long m1 = k1.x > k1.y ? k1.x : k1.y;
        unsigned long long m2 = k2.x > k2.y ? k2.x : k2.y;
        unsigned long long m3 = k3.x > k3.y ? k3.x : k3.y;
        unsigned long long ma = m0 > m1 ? m0 : m1;
        unsigned long long mb = m2 > m3 ? m2 : m3;
        unsigned long long mm = ma > mb ? ma : mb;
        far = 4095 - (int)(unsigned)(mm & 0xffffffffull);
    }
}

// ---------------------------------------------------------------------------
// Kernel 2: ball query — standalone (high occupancy, ~15us)
// ---------------------------------------------------------------------------
__global__ __launch_bounds__(256) void query_kernel(const float* __restrict__ xyz,
                                                    const float* __restrict__ new_xyz)
{
    const int warp = threadIdx.x >> 5, lane = threadIdx.x & 31;
    const int gs = blockIdx.x * 8 + warp;
    const int b  = gs >> 10;
    const float* nc = new_xyz + (size_t)gs * 3;
    const float cx = nc[0], cy = nc[1], cz = nc[2];
    const float* gx = xyz + (size_t)b * NPTS * 3;
    int* out = d_ball + (size_t)gs * KNBR;
    const float R2 = 0.04f;

    int cnt = 0, first = -1;
    for (int base = 0; base < NPTS && cnt < KNBR; base += 32) {
        int j = base + lane;
        float dx = __fsub_rn(cx, gx[3 * j]);
        float dy = __fsub_rn(cy, gx[3 * j + 1]);
        float dz = __fsub_rn(cz, gx[3 * j + 2]);
        float d2 = __fadd_rn(__fadd_rn(__fmul_rn(dx, dx), __fmul_rn(dy, dy)),
                             __fmul_rn(dz, dz));
        bool in = (d2 <= R2);
        unsigned m = __ballot_sync(FULLM, in);
        int pos = cnt + __popc(m & ((1u << lane) - 1u));
        if (in && pos < KNBR) {
            out[pos] = j;
            if (pos == 0) first = j;
        }
        cnt += __popc(m);
    }
    unsigned hf = __ballot_sync(FULLM, first >= 0);
    int src = __ffs(hf) - 1;
    first = __shfl_sync(FULLM, first, src);
    int filled = cnt < KNBR ? cnt : KNBR;
    if (lane >= filled) out[lane] = first;
}

// ---------------------------------------------------------------------------
// Kernel 3: MLP — single-term fp16 (R13 math, bit-identical output).
// Register-lean gather (immediate float4->fp16x2) + launch_bounds(256,2)
// for 2 CTAs/SM.
// ---------------------------------------------------------------------------
#define ASTRIDE  176
#define WSTR1    176
#define WSTR23   144
#define SM_BIAS  0
#define SM_W1F   1024          // 64 x 176B -> 11264
#define SM_W2F   12288         // 64 x 144B -> 9216
#define SM_W3F   21504         // 128 x 144B -> 18432
#define SM_ACT   39936         // 8 warps x 5632B
#define ACTW     5632
#define SM_MLP_END (39936 + 8 * ACTW)   // 84992

__device__ __forceinline__ unsigned cvtf16(float lo, float hi) {
    unsigned r;
    asm("cvt.rn.f16x2.f32 %0, %1, %2;" : "=r"(r) : "f"(hi), "f"(lo));
    return r;
}
__device__ __forceinline__ uint32_t smem_u32(const void* p) {
    uint32_t a;
    asm("{ .reg .u64 t; cvta.to.shared.u64 t, %1; cvt.u32.u64 %0, t; }" : "=r"(a) : "l"(p));
    return a;
}
__device__ __forceinline__ void ldsm4(uint32_t* r, uint32_t addr) {
    asm volatile("ldmatrix.sync.aligned.m8n8.x4.shared.b16 {%0,%1,%2,%3}, [%4];"
        : "=r"(r[0]), "=r"(r[1]), "=r"(r[2]), "=r"(r[3]) : "r"(addr));
}
__device__ __forceinline__ void ldsm2(uint32_t* r, uint32_t addr) {
    asm volatile("ldmatrix.sync.aligned.m8n8.x2.shared.b16 {%0,%1}, [%2];"
        : "=r"(r[0]), "=r"(r[1]) : "r"(addr));
}
__device__ __forceinline__ void mma_f16(float* d, const uint32_t* a, const uint32_t* b) {
    asm volatile("mma.sync.aligned.m16n8k16.row.col.f32.f16.f16.f32 "
        "{%0,%1,%2,%3}, {%4,%5,%6,%7}, {%8,%9}, {%0,%1,%2,%3};"
        : "+f"(d[0]), "+f"(d[1]), "+f"(d[2]), "+f"(d[3])
        : "r"(a[0]), "r"(a[1]), "r"(a[2]), "r"(a[3]), "r"(b[0]), "r"(b[1]));
}

__device__ __forceinline__ void run_layer1_1t(uint32_t aH, uint32_t wFb,
                                              float acc[2][8][4])
{
#pragma unroll
    for (int m = 0; m < 2; m++)
#pragma unroll
        for (int n = 0; n < 8; n++)
#pragma unroll
            for (int q = 0; q < 4; q++) acc[m][n][q] = 0.f;
#pragma unroll
    for (int k = 0; k < 5; k++) {
        uint32_t ah[2][4];
        ldsm4(ah[0], aH + k * 32);
        ldsm4(ah[1], aH + 16 * ASTRIDE + k * 32);
        uint32_t bw[8][2];
#pragma unroll
        for (int n = 0; n < 8; n++)
            ldsm2(bw[n], wFb + n * 8 * WSTR1 + k * 32);
#pragma unroll
        for (int n = 0; n < 8; n++)
#pragma unroll
            for (int m = 0; m < 2; m++)
                mma_f16(acc[m][n], ah[m], bw[n]);
    }
}

__device__ __forceinline__ void build_frag_1t(const float acc[2][8][4],
                                              const float* bias, int cg,
                                              uint32_t af[2][4][4])
{
#pragma unroll
    for (int m = 0; m < 2; m++) {
#pragma unroll
        for (int j = 0; j < 4; j++) {
            const float* a0 = acc[m][2 * j];
            const float* a1 = acc[m][2 * j + 1];
            float bA0 = bias[(2 * j) * 8 + 2 * cg],     bB0 = bias[(2 * j) * 8 + 2 * cg + 1];
            float bA1 = bias[(2 * j + 1) * 8 + 2 * cg], bB1 = bias[(2 * j + 1) * 8 + 2 * cg + 1];
            float x0 = fmaxf(a0[0] + bA0, 0.f), x1 = fmaxf(a0[1] + bB0, 0.f);
            float x2 = fmaxf(a0[2] + bA0, 0.f), x3 = fmaxf(a0[3] + bB0, 0.f);
            float x4 = fmaxf(a1[0] + bA1, 0.f), x5 = fmaxf(a1[1] + bB1, 0.f);
            float x6 = fmaxf(a1[2] + bA1, 0.f), x7 = fmaxf(a1[3] + bB1, 0.f);
            af[m][j][0] = cvtf16(x0, x1);
            af[m][j][1] = cvtf16(x2, x3);
            af[m][j][2] = cvtf16(x4, x5);
            af[m][j][3] = cvtf16(x6, x7);
        }
    }
}

__device__ __forceinline__ void run_layer_1t(const uint32_t af[2][4][4],
                                             uint32_t wFb,
                                             float acc[2][8][4])
{
#pragma unroll
    for (int m = 0; m < 2; m++)
#pragma unroll
        for (int n = 0; n < 8; n++)
#pragma unroll
            for (int q = 0; q < 4; q++) acc[m][n][q] = 0.f;
#pragma unroll
    for (int k = 0; k < 4; k++) {
        uint32_t bw[8][2];
#pragma unroll
        for (int n = 0; n < 8; n++)
            ldsm2(bw[n], wFb + n * 8 * WSTR23 + k * 32);
#pragma unroll
        for (int n = 0; n < 8; n++)
#pragma unroll
            for (int m = 0; m < 2; m++)
                mma_f16(acc[m][n], af[m][k], bw[n]);
    }
}

__device__ __forceinline__ void epi_max(float acc[2][8][4], const float* bias,
                                        float* outp, int nbase, int lane)
{
    const int cg = lane & 3;
#pragma unroll
    for (int n = 0; n < 8; n++) {
        int n0 = nbase + n * 8 + 2 * cg;
        float b0v = bias[n0], b1v = bias[n0 + 1];
        float v0 = fmaxf(fmaxf(acc[0][n][0] + b0v, 0.f), fmaxf(acc[0][n][2] + b0v, 0.f));
        v0 = fmaxf(v0, fmaxf(fmaxf(acc[1][n][0] + b0v, 0.f), fmaxf(acc[1][n][2] + b0v, 0.f)));
        float v1 = fmaxf(fmaxf(acc[0][n][1] + b1v, 0.f), fmaxf(acc[0][n][3] + b1v, 0.f));
        v1 = fmaxf(v1, fmaxf(fmaxf(acc[1][n][1] + b1v, 0.f), fmaxf(acc[1][n][3] + b1v, 0.f)));
#pragma unroll
        for (int o = 4; o <= 16; o <<= 1) {
            v0 = fmaxf(v0, __shfl_xor_sync(FULLM, v0, o));
            v1 = fmaxf(v1, __shfl_xor_sync(FULLM, v1, o));
        }
        if (lane < 4) { outp[n0] = v0; outp[n0 + 1] = v1; }
    }
}

__global__ __launch_bounds__(256, 2) void mlp_kernel(
    const float* __restrict__ xyz, const float* __restrict__ pts,
    const float* __restrict__ w0, const float* __restrict__ b0,
    const float* __restrict__ w1, const float* __restrict__ b1,
    const float* __restrict__ w2, const float* __restrict__ b2,
    const float* __restrict__ new_xyz, float* __restrict__ new_points)
{
    extern __shared__ char smem[];
    const uint32_t sb = smem_u32(smem);
    const int tid = threadIdx.x, wid = tid >> 5, lane = tid & 31;

    float* b0s = (float*)(smem + SM_BIAS);
    float* b1s = b0s + 64;
    float* b2s = b1s + 64;
    if (tid < 64) { b0s[tid] = b0[tid]; b1s[tid] = b1[tid]; }
    if (tid < 128) b2s[tid] = b2[tid];

    for (int idx = tid; idx < 64 * 80; idx += 256) {
        int n = idx / 80, k = idx - n * 80;
        float w = (k < 67) ? w0[k * 64 + n] : 0.f;
        *(unsigned short*)(smem + SM_W1F + n * WSTR1 + k * 2) =
            __half_as_ushort(__float2half_rn(w));
    }
    for (int idx = tid; idx < 64 * 64; idx += 256) {
        int n = idx >> 6, k = idx & 63;
        *(unsigned short*)(smem + SM_W2F + n * WSTR23 + k * 2) =
            __half_as_ushort(__float2half_rn(w1[k * 64 + n]));
    }
    for (int idx = tid; idx < 128 * 64; idx += 256) {
        int n = idx >> 6, k = idx & 63;
        *(unsigned short*)(smem + SM_W3F + n * WSTR23 + k * 2) =
            __half_as_ushort(__float2half_rn(w2[k * 128 + n]));
    }
    __syncthreads();

    char* actHp = smem + SM_ACT + wid * ACTW;
    const uint32_t actH_u = sb + SM_ACT + wid * ACTW;
    const uint32_t aH = actH_u + (lane & 15) * ASTRIDE + (lane >> 4) * 16;
    const int bl = lane & 15;
    const uint32_t wl1 = (bl & 7) * WSTR1  + ((bl >> 3) & 1) * 16;
    const uint32_t wl2 = (bl & 7) * WSTR23 + ((bl >> 3) & 1) * 16;
    const uint32_t w1F = sb + SM_W1F + wl1;
    const uint32_t w2F = sb + SM_W2F + wl2;
    const uint32_t w3F = sb + SM_W3F + wl2;
    const int cg = lane & 3;

#pragma unroll 1
    for (int cc = 0; cc < 4; cc++) {
        const int centroid = blockIdx.x * 32 + wid * 4 + cc;
        const int b = centroid >> 10;
        const int nid = d_ball[(size_t)centroid * KNBR + lane];

        __syncwarp();
        // ---- gather: convert immediately, no register staging buffer ----
        {
            uint32_t* rowH = (uint32_t*)(actHp + lane * ASTRIDE);
            const float4* pr = (const float4*)(pts + ((size_t)b * NPTS + nid) * CIN);
#pragma unroll
            for (int q = 0; q < 16; q++) {
                float4 v = pr[q];
                rowH[2 * q]     = cvtf16(v.x, v.y);
                rowH[2 * q + 1] = cvtf16(v.z, v.w);
            }
            const float* xr = xyz + ((size_t)b * NPTS + nid) * 3;
            const float* nc = new_xyz + (size_t)centroid * 3;
            float rx = __fsub_rn(xr[0], nc[0]);
            float ry = __fsub_rn(xr[1], nc[1]);
            float rz = __fsub_rn(xr[2], nc[2]);
            rowH[32] = cvtf16(rx, ry);
            rowH[33] = cvtf16(rz, 0.f);
#pragma unroll
            for (int i = 34; i < 40; i++) rowH[i] = 0u;
        }
        __syncwarp();

        float acc[2][8][4];
        run_layer1_1t(aH, w1F, acc);
        __syncwarp();

        uint32_t af[2][4][4];
        build_frag_1t(acc, b0s, cg, af);
        run_layer_1t(af, w2F, acc);
        build_frag_1t(acc, b1s, cg, af);
        float* outp = new_points + (size_t)centroid * 128;
        run_layer_1t(af, w3F, acc);
        epi_max(acc, b2s, outp, 0, lane);
        run_layer_1t(af, w3F + 64 * WSTR23, acc);
        epi_max(acc, b2s, outp, 64, lane);
    }
}

// ---------------------------------------------------------------------------
extern "C" void kernel_launch(void* const* d_in, const int* in_sizes, int n_in,
                              void* d_out, int out_size)
{
    (void)in_sizes; (void)n_in; (void)out_size;
    const float* xyz = (const float*)d_in[0];
    const float* pts = (const float*)d_in[1];
    const float* w0  = (const float*)d_in[2];
    const float* b0  = (const float*)d_in[3];
    const float* w1  = (const float*)d_in[4];
    const float* b1  = (const float*)d_in[5];
    const float* w2  = (const float*)d_in[6];
    const float* b2  = (const float*)d_in[7];

    float* out      = (float*)d_out;
    float* new_xyz  = out;
    float* new_pts  = out + (size_t)BATCH * NSAMP * 3;

    const int FPS_SMEM = NPTS * 16 + 128;
    const int MLP_SMEM = SM_MLP_END;

    cudaFuncSetAttribute(fps_kernel, cudaFuncAttributeMaxDynamicSharedMemorySize, FPS_SMEM);
    cudaFuncSetAttribute(mlp_kernel, cudaFuncAttributeMaxDynamicSharedMemorySize, MLP_SMEM);

    fps_kernel<<<BATCH, 256, FPS_SMEM>>>(xyz, new_xyz);
    query_kernel<<<(BATCH * NSAMP) / 8, 256>>>(xyz, new_xyz);
    mlp_kernel<<<(BATCH * NSAMP) / 32, 256, MLP_SMEM>>>(
        xyz, pts, w0, b0, w1, b1, w2, b2, new_xyz, new_pts);
}